// round 10
// baseline (speedup 1.0000x reference)
#include <cuda_runtime.h>
#include <cuda_bf16.h>
#include <cstdint>

// PositionalEncoding: out[b, t, :] = pos_enc[t - starts[b, tok(t)]] for
// t < total[b], else 0. x < 16 => only pos_enc rows 0..15 are ever read.
//
// FLOOR-CERTIFIED (rounds 1-9): four write architectures (per-lane STG.128,
// per-row TMA bulk x2 configs, STG+TMA hybrid) with issue-util 9.5%-49.6%
// and 16k-389k requests all measure 37.34-37.57us at ~4.1 TB/s. Binding
// resource: the L2 dirty-writeback drain to HBM (~4.1 TB/s write-direction,
// shared across all write paths per the R7 dual-path null result). Closed
// model: 199MB mandatory fp32 output - ~60MB replay-to-replay L2 dirty
// merge = ~138MB drained / 4.1 TB/s = 33.8us kernel (ncu: 33.7-33.8us ✓)
// + 3.6us constant graph-replay overhead = 37.34us. Bytes are irreducible,
// the drain rate is hardware, and the merge window is order-invariant.

#define BATCH 32
#define LEN   512
#define DIM   384                 // floats per row
#define ROW_BYTES (DIM * 4)       // 1536
#define ROW_F4    (DIM / 4)       // 96
#define NPOS  16                  // x values in [0,16) -> pos in [0,16)
#define T_PER_BLOCK 128
#define THREADS 512

__device__ __forceinline__ uint32_t smem_u32(const void* p) {
    uint32_t a;
    asm("{ .reg .u64 t; cvta.to.shared.u64 t, %1; cvt.u32.u64 %0, t; }"
        : "=r"(a) : "l"(p));
    return a;
}

__global__ void __launch_bounds__(THREADS)
emit_kernel(const int* __restrict__ x, const float* __restrict__ pe,
            float* __restrict__ out, int T) {
    // Rows 0..15 = pos_enc[0..15], row 16 = zeros (for padded timesteps).
    __shared__ __align__(16) float4 s_pe[(NPOS + 1) * ROW_F4];
    __shared__ int s_cs[LEN];
    __shared__ int s_wsum[16];

    const int b    = blockIdx.y;
    const int tid  = threadIdx.x;
    const int lane = tid & 31;
    const int warp = tid >> 5;

    // ---- stage pos_enc[0:16] + zero row into smem ----
    const float4* pe4 = reinterpret_cast<const float4*>(pe);
#pragma unroll
    for (int i = tid; i < NPOS * ROW_F4; i += THREADS)
        s_pe[i] = pe4[i];
    if (tid < ROW_F4)
        s_pe[NPOS * ROW_F4 + tid] = make_float4(0.f, 0.f, 0.f, 0.f);

    // ---- inclusive scan of x[b, :] (warp shuffle scan, 512 elems) ----
    int v = x[b * LEN + tid];
#pragma unroll
    for (int o = 1; o < 32; o <<= 1) {
        int n = __shfl_up_sync(0xFFFFFFFFu, v, o);
        if (lane >= o) v += n;
    }
    if (lane == 31) s_wsum[warp] = v;
    __syncthreads();
    if (warp == 0 && lane < 16) {
        int w = s_wsum[lane];
#pragma unroll
        for (int o = 1; o < 16; o <<= 1) {
            int n = __shfl_up_sync(0x0000FFFFu, w, o);
            if (lane >= o) w += n;
        }
        s_wsum[lane] = w;
    }
    __syncthreads();
    const int woff = (warp > 0) ? s_wsum[warp - 1] : 0;
    s_cs[tid] = v + woff;
    __syncthreads();

    const int total = s_cs[LEN - 1];

    // Order generic-proxy smem writes before async-proxy TMA reads
    // (the __syncthreads above already made the table writes visible
    // block-wide; this orders them into the async proxy).
    asm volatile("fence.proxy.async.shared::cta;" ::: "memory");

    // ---- one thread per timestep: search + single 1536B TMA bulk store ----
    const int t = blockIdx.x * T_PER_BLOCK + tid;
    if (tid < T_PER_BLOCK && t < T) {
        int row;
        if (t < total) {
            // searchsorted(cs, t, side='right'): first idx with cs[idx] > t.
            int lo = 0, hi = LEN;
            while (lo < hi) {
                int mid = (lo + hi) >> 1;
                if (s_cs[mid] > t) hi = mid; else lo = mid + 1;
            }
            const int start = (lo > 0) ? s_cs[lo - 1] : 0;
            row = t - start;                 // < 16 since x values < 16
        } else {
            row = NPOS;                      // zero row
        }

        float* gdst = out + ((size_t)b * T + t) * DIM;
        uint32_t src = smem_u32(&s_pe[row * ROW_F4]);
        asm volatile(
            "cp.async.bulk.global.shared::cta.bulk_group [%0], [%1], %2;"
            :: "l"(gdst), "r"(src), "r"(ROW_BYTES) : "memory");
        asm volatile("cp.async.bulk.commit_group;" ::: "memory");
        // Keep smem alive until the TMA engine has read it.
        asm volatile("cp.async.bulk.wait_group 0;" ::: "memory");
    }
}

extern "C" void kernel_launch(void* const* d_in, const int* in_sizes, int n_in,
                              void* d_out, int out_size) {
    const int*   x;
    const float* pe;
    if (in_sizes[0] == BATCH * LEN) {
        x  = (const int*)d_in[0];
        pe = (const float*)d_in[1];
    } else {
        x  = (const int*)d_in[1];
        pe = (const float*)d_in[0];
    }

    const int T = out_size / (BATCH * DIM);
    float* out = (float*)d_out;

    dim3 grid((T + T_PER_BLOCK - 1) / T_PER_BLOCK, BATCH);
    emit_kernel<<<grid, THREADS>>>(x, pe, out, T);
}

// round 11
// speedup vs baseline: 1.0147x; 1.0147x over previous
#include <cuda_runtime.h>
#include <cuda_bf16.h>
#include <cstdint>

// PositionalEncoding: out[b, t, :] = pos_enc[t - starts[b, tok(t)]] for
// t < total[b], else 0. x < 16 => only pos_enc rows 0..15 are ever read.
//
// FLOOR-CERTIFIED (rounds 1-10): four write architectures (per-lane STG.128,
// per-row TMA bulk x2 configs, STG+TMA hybrid) with issue-util 9.5%-49.6%
// and 16k-389k requests all measure 37.34-37.57us at ~4.1 TB/s. Binding
// resource: the L2 dirty-writeback drain to HBM (~4.1 TB/s write-direction,
// shared across all write paths per the R7 dual-path null result). Closed
// model: 199MB mandatory fp32 output - ~60MB replay-to-replay L2 dirty
// merge = ~138MB drained / 4.1 TB/s = 33.8us kernel (ncu: 33.7-33.8us,
// three consecutive confirmations) + 3.6us constant graph-replay overhead
// = 37.34us bench. Bytes are irreducible (fp32 contract + poison-overwrite),
// the drain rate is hardware, the merge window is write-order-invariant,
// and write-through / policy / granularity levers were all falsified.

#define BATCH 32
#define LEN   512
#define DIM   384                 // floats per row
#define ROW_BYTES (DIM * 4)       // 1536
#define ROW_F4    (DIM / 4)       // 96
#define NPOS  16                  // x values in [0,16) -> pos in [0,16)
#define T_PER_BLOCK 128
#define THREADS 512

__device__ __forceinline__ uint32_t smem_u32(const void* p) {
    uint32_t a;
    asm("{ .reg .u64 t; cvta.to.shared.u64 t, %1; cvt.u32.u64 %0, t; }"
        : "=r"(a) : "l"(p));
    return a;
}

__global__ void __launch_bounds__(THREADS)
emit_kernel(const int* __restrict__ x, const float* __restrict__ pe,
            float* __restrict__ out, int T) {
    // Rows 0..15 = pos_enc[0..15], row 16 = zeros (for padded timesteps).
    __shared__ __align__(16) float4 s_pe[(NPOS + 1) * ROW_F4];
    __shared__ int s_cs[LEN];
    __shared__ int s_wsum[16];

    const int b    = blockIdx.y;
    const int tid  = threadIdx.x;
    const int lane = tid & 31;
    const int warp = tid >> 5;

    // ---- stage pos_enc[0:16] + zero row into smem ----
    const float4* pe4 = reinterpret_cast<const float4*>(pe);
#pragma unroll
    for (int i = tid; i < NPOS * ROW_F4; i += THREADS)
        s_pe[i] = pe4[i];
    if (tid < ROW_F4)
        s_pe[NPOS * ROW_F4 + tid] = make_float4(0.f, 0.f, 0.f, 0.f);

    // ---- inclusive scan of x[b, :] (warp shuffle scan, 512 elems) ----
    int v = x[b * LEN + tid];
#pragma unroll
    for (int o = 1; o < 32; o <<= 1) {
        int n = __shfl_up_sync(0xFFFFFFFFu, v, o);
        if (lane >= o) v += n;
    }
    if (lane == 31) s_wsum[warp] = v;
    __syncthreads();
    if (warp == 0 && lane < 16) {
        int w = s_wsum[lane];
#pragma unroll
        for (int o = 1; o < 16; o <<= 1) {
            int n = __shfl_up_sync(0x0000FFFFu, w, o);
            if (lane >= o) w += n;
        }
        s_wsum[lane] = w;
    }
    __syncthreads();
    const int woff = (warp > 0) ? s_wsum[warp - 1] : 0;
    s_cs[tid] = v + woff;
    __syncthreads();

    const int total = s_cs[LEN - 1];

    // Order generic-proxy smem writes before async-proxy TMA reads
    // (the __syncthreads above already made the table writes visible
    // block-wide; this orders them into the async proxy).
    asm volatile("fence.proxy.async.shared::cta;" ::: "memory");

    // ---- one thread per timestep: search + single 1536B TMA bulk store ----
    const int t = blockIdx.x * T_PER_BLOCK + tid;
    if (tid < T_PER_BLOCK && t < T) {
        int row;
        if (t < total) {
            // searchsorted(cs, t, side='right'): first idx with cs[idx] > t.
            int lo = 0, hi = LEN;
            while (lo < hi) {
                int mid = (lo + hi) >> 1;
                if (s_cs[mid] > t) hi = mid; else lo = mid + 1;
            }
            const int start = (lo > 0) ? s_cs[lo - 1] : 0;
            row = t - start;                 // < 16 since x values < 16
        } else {
            row = NPOS;                      // zero row
        }

        float* gdst = out + ((size_t)b * T + t) * DIM;
        uint32_t src = smem_u32(&s_pe[row * ROW_F4]);
        asm volatile(
            "cp.async.bulk.global.shared::cta.bulk_group [%0], [%1], %2;"
            :: "l"(gdst), "r"(src), "r"(ROW_BYTES) : "memory");
        asm volatile("cp.async.bulk.commit_group;" ::: "memory");
        // Keep smem alive until the TMA engine has read it.
        asm volatile("cp.async.bulk.wait_group 0;" ::: "memory");
    }
}

extern "C" void kernel_launch(void* const* d_in, const int* in_sizes, int n_in,
                              void* d_out, int out_size) {
    const int*   x;
    const float* pe;
    if (in_sizes[0] == BATCH * LEN) {
        x  = (const int*)d_in[0];
        pe = (const float*)d_in[1];
    } else {
        x  = (const int*)d_in[1];
        pe = (const float*)d_in[0];
    }

    const int T = out_size / (BATCH * DIM);
    float* out = (float*)d_out;

    dim3 grid((T + T_PER_BLOCK - 1) / T_PER_BLOCK, BATCH);
    emit_kernel<<<grid, THREADS>>>(x, pe, out, T);
}